// round 16
// baseline (speedup 1.0000x reference)
#include <cuda_runtime.h>
#include <math.h>

// Problem constants
#define BB 64          // batch
#define TT 512         // time steps
#define HH 1024        // hidden
#define EE 300         // embedding dim

#define GRID_SCAN 128  // persistent blocks, 1 block/SM via SMEM => all co-resident
#define TPB_SCAN  512  // 16 warps = 4 per SMSP
#define HB 8           // h-rows owned per scan block (128*8 = 1024)

typedef unsigned long long ull;

// ---------------- device scratch (no allocations allowed) ----------------
__device__ __align__(256) float g_pre0[(size_t)TT * HH * BB]; // [t][h][b], 128 MB
__device__ __align__(256) float g_h1[2][HH * BB];             // ping-pong [h][b]
__device__ __align__(256) float g_h2[2][HH * BB];
__device__ unsigned             g_bar;

// ---------------- packed f32x2 helpers ----------------
#define FFMA2(d, a, b) asm("fma.rn.f32x2 %0, %1, %2, %0;" : "+l"(d) : "l"(a), "l"(b))
#define FADD2(d, a)    asm("add.rn.f32x2 %0, %0, %1;"     : "+l"(d) : "l"(a))

union F4U { float4 f; ull u[2]; };

// Monotone grid barrier (R9-proven): counter zeroed by k_init each launch.
__device__ __forceinline__ void gsync(unsigned n) {
    __threadfence();
    __syncthreads();
    if (threadIdx.x == 0) {
        atomicAdd(&g_bar, 1u);
        const unsigned tgt = n * GRID_SCAN;
        while (*((volatile unsigned*)&g_bar) < tgt) { }
    }
    __syncthreads();
}

// 16 packed FMAs: 8 h-rows (4 float4 of (w,w) pairs) x 4 b (2 packed pairs)
__device__ __forceinline__ void mat16(ull* acc, const float4* W, const ull* su) {
    F4U q0, q1, q2, q3;
    q0.f = W[0]; q1.f = W[1]; q2.f = W[2]; q3.f = W[3];
    FFMA2(acc[ 0], q0.u[0], su[0]); FFMA2(acc[ 1], q0.u[0], su[1]);
    FFMA2(acc[ 2], q0.u[1], su[0]); FFMA2(acc[ 3], q0.u[1], su[1]);
    FFMA2(acc[ 4], q1.u[0], su[0]); FFMA2(acc[ 5], q1.u[0], su[1]);
    FFMA2(acc[ 6], q1.u[1], su[0]); FFMA2(acc[ 7], q1.u[1], su[1]);
    FFMA2(acc[ 8], q2.u[0], su[0]); FFMA2(acc[ 9], q2.u[0], su[1]);
    FFMA2(acc[10], q2.u[1], su[0]); FFMA2(acc[11], q2.u[1], su[1]);
    FFMA2(acc[12], q3.u[0], su[0]); FFMA2(acc[13], q3.u[0], su[1]);
    FFMA2(acc[14], q3.u[1], su[0]); FFMA2(acc[15], q3.u[1], su[1]);
}

// ======================================================================
// Kernel 1: pre0[t][h][b] = sum_e emb[x[b][t]][e]*W_ih0[h][e] + b_ih0[h] + b_hh0[h]
// ======================================================================
__global__ void k_pre0(const int* __restrict__ x, const float* __restrict__ emb,
                       const float* __restrict__ Wih0,
                       const float* __restrict__ bih0, const float* __restrict__ bhh0) {
    extern __shared__ float sm[];
    float*  As  = sm;                       // [300][64]  As[c*64 + b]
    float2* Ws2 = (float2*)(sm + EE * 64);  // [300][64]  (w,w) pairs
    __shared__ int toks[64];

    const int tid   = threadIdx.x;
    const int t     = blockIdx.y;
    const int hbase = blockIdx.x * 64;

    if (tid < 64) toks[tid] = x[tid * TT + t];
    __syncthreads();

    for (int idx = tid; idx < 64 * EE; idx += 256) {
        int r = idx / EE, c = idx - r * EE;
        As[c * 64 + r] = emb[(size_t)toks[r] * EE + c];
        float wv = Wih0[(size_t)(hbase + r) * EE + c];
        Ws2[c * 64 + r] = make_float2(wv, wv);
    }
    __syncthreads();

    const int tx = tid & 15;    // b-quad
    const int ty = tid >> 4;    // h-quad
    ull acc2[4][2];
#pragma unroll
    for (int j = 0; j < 4; j++) { acc2[j][0] = 0ull; acc2[j][1] = 0ull; }

#pragma unroll 4
    for (int c = 0; c < EE; c++) {
        ull a01 = *(const ull*)(As + c * 64 + tx * 4);
        ull a23 = *(const ull*)(As + c * 64 + tx * 4 + 2);
        F4U w01, w23;
        w01.f = *(const float4*)(Ws2 + c * 64 + ty * 4);
        w23.f = *(const float4*)(Ws2 + c * 64 + ty * 4 + 2);
        FFMA2(acc2[0][0], w01.u[0], a01); FFMA2(acc2[0][1], w01.u[0], a23);
        FFMA2(acc2[1][0], w01.u[1], a01); FFMA2(acc2[1][1], w01.u[1], a23);
        FFMA2(acc2[2][0], w23.u[0], a01); FFMA2(acc2[2][1], w23.u[0], a23);
        FFMA2(acc2[3][0], w23.u[1], a01); FFMA2(acc2[3][1], w23.u[1], a23);
    }

#pragma unroll
    for (int j = 0; j < 4; j++) {
        int h = hbase + ty * 4 + j;
        float bs = bih0[h] + bhh0[h];
        F4U o; o.u[0] = acc2[j][0]; o.u[1] = acc2[j][1];
        float4 v = make_float4(o.f.x + bs, o.f.y + bs, o.f.z + bs, o.f.w + bs);
        *(float4*)(&g_pre0[((size_t)t * HH + h) * BB + tx * 4]) = v;
    }
}

// ======================================================================
// Kernel 2: persistent scan. Iter t computes h1[t] AND h2[t-1] (lagged),
// ONE grid barrier per iter. 16 warps (4/SMSP), k split 16 ways;
// two-level warp-partial reduction (red buffer stays 32 KB).
// ======================================================================
__global__ void __launch_bounds__(TPB_SCAN, 1)
k_scan(const float* __restrict__ Whh0, const float* __restrict__ Wih1,
       const float* __restrict__ Whh1,
       const float* __restrict__ bih1, const float* __restrict__ bhh1) {
    extern __shared__ float sm[];
    float2* wp0    = (float2*)sm;            // [1024][8] (w,w) pairs, 64 KB
    float2* wpA    = wp0 + 8192;             // Wih1
    float2* wpB    = wpA + 8192;             // Whh1
    float*  red    = (float*)(wpB + 8192);   // [8 slots][2 mats][8 h][64 b], 32 KB
    float*  bias2s = red + 8192;             // [8]

    const int g    = blockIdx.x;
    const int tid  = threadIdx.x;
    const int w    = tid >> 5;        // 0..15
    const int lane = tid & 31;
    const int bq   = lane >> 1;       // 0..15
    const int kl   = lane & 1;
    const int b4   = bq * 4;

    // Finale mapping (threads 0..255)
    const int matf = (tid >> 7) & 1;
    const int hlf  = (tid >> 4) & 7;
    const int b0f  = (tid & 15) * 4;

    // Load + transpose + duplicate this block's weight rows (one-time).
    for (int idx = tid; idx < HB * HH; idx += TPB_SCAN) {
        int j = idx >> 10, kk = idx & 1023;
        float v0 = Whh0[(size_t)(g * HB + j) * HH + kk];
        float va = Wih1[(size_t)(g * HB + j) * HH + kk];
        float vb = Whh1[(size_t)(g * HB + j) * HH + kk];
        wp0[kk * 8 + j] = make_float2(v0, v0);
        wpA[kk * 8 + j] = make_float2(va, va);
        wpB[kk * 8 + j] = make_float2(vb, vb);
    }
    if (tid < HB) bias2s[tid] = bih1[g * HB + tid] + bhh1[g * HB + tid];
    __syncthreads();

    const int k0 = w * 64 + kl;       // thread's first k; step 2, 32 iters
    unsigned syncno = 0;

    for (int t = 0; t <= TT; t++) {
        const float* s1base = g_h1[(t + 1) & 1];   // h1[t-1]
        const float* s2base = g_h2[t & 1];         // h2[t-2]

        // Early prefetch of this step's pre0 operand for the finale (DRAM).
        float4 pre_pref;
        if (tid < 256 && matf == 0 && t < TT)
            pre_pref = __ldg((const float4*)&g_pre0[((size_t)t * HH + g * HB + hlf) * BB + b0f]);

        ull a1[16], a2[16];
#pragma unroll
        for (int i = 0; i < 16; i++) { a1[i] = 0ull; a2[i] = 0ull; }

        const float*  p1 = s1base + (size_t)k0 * BB + b4;
        const float*  p2 = s2base + (size_t)k0 * BB + b4;
        const float4* w0f4 = (const float4*)wp0 + (size_t)k0 * 4;
        const float4* wAf4 = (const float4*)wpA + (size_t)k0 * 4;
        const float4* wBf4 = (const float4*)wpB + (size_t)k0 * 4;

        F4U A1[2], A2[2], B1[2], B2[2];
#pragma unroll
        for (int j = 0; j < 2; j++) {                 // preload iters 0,1
            A1[j].f = __ldcg((const float4*)(p1 + (size_t)j * 128));
            A2[j].f = __ldcg((const float4*)(p2 + (size_t)j * 128));
        }

        auto do2 = [&](F4U* c1, F4U* c2, F4U* n1, F4U* n2, int base) {
            // batch-prefetch the NEXT 2 iters (distance 2..4 iters ahead)
#pragma unroll
            for (int j = 0; j < 2; j++) {
                int it = base + 2 + j;
                if (it < 32) {
                    n1[j].f = __ldcg((const float4*)(p1 + (size_t)it * 128));
                    n2[j].f = __ldcg((const float4*)(p2 + (size_t)it * 128));
                }
            }
#pragma unroll
            for (int j = 0; j < 2; j++) {
                int i = base + j;
                mat16(a1, w0f4 + (size_t)i * 8, c1[j].u);
                mat16(a2, wAf4 + (size_t)i * 8, c1[j].u);
                mat16(a2, wBf4 + (size_t)i * 8, c2[j].u);
            }
        };

        for (int base = 0; base < 32; base += 4) {
            do2(A1, A2, B1, B2, base);
            do2(B1, B2, A1, A2, base + 2);
        }

        // Reduce across klane (adjacent lanes) with 64-bit shfl + packed add.
#pragma unroll
        for (int i = 0; i < 16; i++) {
            ull o1 = __shfl_xor_sync(0xffffffffu, a1[i], 1); FADD2(a1[i], o1);
            ull o2 = __shfl_xor_sync(0xffffffffu, a2[i], 1); FADD2(a2[i], o2);
        }

        // Level 1: warps 8..15 (klane 0) store partials to slot w-8.
        if (kl == 0 && w >= 8) {
            const int slot = w - 8;
#pragma unroll
            for (int h = 0; h < 8; h++) {
                F4U o;
                o.u[0] = a1[h * 2]; o.u[1] = a1[h * 2 + 1];
                *(float4*)&red[((slot * 2 + 0) * 8 + h) * 64 + b4] = o.f;
                o.u[0] = a2[h * 2]; o.u[1] = a2[h * 2 + 1];
                *(float4*)&red[((slot * 2 + 1) * 8 + h) * 64 + b4] = o.f;
            }
        }
        __syncthreads();

        // Level 2: warps 0..7 (klane 0) fold partner partials in, store to slot w.
        // (NO __syncwarp here — divergent full-mask syncwarp was the R11 deadlock.)
        if (kl == 0 && w < 8) {
#pragma unroll
            for (int h = 0; h < 8; h++) {
                F4U o1, o2;
                o1.f = *(const float4*)&red[((w * 2 + 0) * 8 + h) * 64 + b4];
                o2.f = *(const float4*)&red[((w * 2 + 1) * 8 + h) * 64 + b4];
                FADD2(a1[h * 2], o1.u[0]); FADD2(a1[h * 2 + 1], o1.u[1]);
                FADD2(a2[h * 2], o2.u[0]); FADD2(a2[h * 2 + 1], o2.u[1]);
            }
#pragma unroll
            for (int h = 0; h < 8; h++) {
                F4U o;
                o.u[0] = a1[h * 2]; o.u[1] = a1[h * 2 + 1];
                *(float4*)&red[((w * 2 + 0) * 8 + h) * 64 + b4] = o.f;
                o.u[0] = a2[h * 2]; o.u[1] = a2[h * 2 + 1];
                *(float4*)&red[((w * 2 + 1) * 8 + h) * 64 + b4] = o.f;
            }
        }
        __syncthreads();

        // Finale: threads 0..255 each own 4 output values.
        if (tid < 256) {
            float4 s = make_float4(0.f, 0.f, 0.f, 0.f);
#pragma unroll
            for (int p = 0; p < 8; p++) {
                float4 v = *(const float4*)&red[((p * 16) + matf * 8 + hlf) * 64 + b0f];
                s.x += v.x; s.y += v.y; s.z += v.z; s.w += v.w;
            }
            if (matf == 0) {
                if (t < TT) {
                    s.x = tanhf(s.x + pre_pref.x); s.y = tanhf(s.y + pre_pref.y);
                    s.z = tanhf(s.z + pre_pref.z); s.w = tanhf(s.w + pre_pref.w);
                    __stcg((float4*)&g_h1[t & 1][(g * HB + hlf) * BB + b0f], s);
                }
            } else if (t > 0) {
                float bb = bias2s[hlf];
                s.x = tanhf(s.x + bb); s.y = tanhf(s.y + bb);
                s.z = tanhf(s.z + bb); s.w = tanhf(s.w + bb);
                // h2[t-1] -> buffer (t-1)&1 == (t+1)&1
                __stcg((float4*)&g_h2[(t + 1) & 1][(g * HB + hlf) * BB + b0f], s);
            }
        }

        if (t < TT) gsync(++syncno);
    }
}

// ======================================================================
// Kernel 3: out[b] = sigmoid(h2[511][:,b] . W_fc + b_fc).  h2[511] is in buf 1.
// ======================================================================
__global__ void k_fc(const float* __restrict__ Wfc, const float* __restrict__ bfc,
                     float* __restrict__ out) {
    __shared__ float redm[256];
    const int tid = threadIdx.x;
    const int b = tid & 63, part = tid >> 6;
    float s = 0.f;
    for (int hh = part * 256; hh < part * 256 + 256; hh++)
        s += g_h2[1][hh * BB + b] * Wfc[hh];
    redm[tid] = s;
    __syncthreads();
    if (tid < 64) {
        float v = redm[tid] + redm[tid + 64] + redm[tid + 128] + redm[tid + 192] + bfc[0];
        out[b] = 1.f / (1.f + expf(-v));
    }
}

// ======================================================================
// Kernel 0: per-launch reset (determinism across graph replays).
// ======================================================================
__global__ void k_init() {
    int i = blockIdx.x * blockDim.x + threadIdx.x;
    if (i == 0) g_bar = 0u;
    if (i < HH * BB) {
        g_h1[0][i] = 0.f; g_h1[1][i] = 0.f;
        g_h2[0][i] = 0.f; g_h2[1][i] = 0.f;
    }
}

// ======================================================================
extern "C" void kernel_launch(void* const* d_in, const int* in_sizes, int n_in,
                              void* d_out, int out_size) {
    const int*   x    = (const int*)  d_in[0];
    const float* emb  = (const float*)d_in[1];
    const float* Wih0 = (const float*)d_in[2];
    const float* Whh0 = (const float*)d_in[3];
    const float* bih0 = (const float*)d_in[4];
    const float* bhh0 = (const float*)d_in[5];
    const float* Wih1 = (const float*)d_in[6];
    const float* Whh1 = (const float*)d_in[7];
    const float* bih1 = (const float*)d_in[8];
    const float* bhh1 = (const float*)d_in[9];
    const float* Wfc  = (const float*)d_in[10];
    const float* bfc  = (const float*)d_in[11];
    float* out = (float*)d_out;

    const int pre0_smem = (EE * 64) * 4 + (EE * 64) * 8;                 // 230,400 B
    const int scan_smem = (3 * 8192) * 8 + 8192 * 4 + 64;                // 229,504 B
    cudaFuncSetAttribute(k_pre0, cudaFuncAttributeMaxDynamicSharedMemorySize, pre0_smem);
    cudaFuncSetAttribute(k_scan, cudaFuncAttributeMaxDynamicSharedMemorySize, scan_smem);

    k_init<<<(HH * BB + 255) / 256, 256>>>();
    k_pre0<<<dim3(HH / 64, TT), 256, pre0_smem>>>(x, emb, Wih0, bih0, bhh0);
    k_scan<<<GRID_SCAN, TPB_SCAN, scan_smem>>>(Whh0, Wih1, Whh1, bih1, bhh1);
    k_fc<<<1, 256>>>(Wfc, bfc, out);
}

// round 17
// speedup vs baseline: 1.4001x; 1.4001x over previous
#include <cuda_runtime.h>
#include <math.h>

// Problem constants
#define BB 64          // batch
#define TT 512         // time steps
#define HH 1024        // hidden
#define EE 300         // embedding dim

#define GRID_SCAN 128  // persistent blocks, 1 block/SM via SMEM => all co-resident
#define TPB_SCAN  512  // 16 warps = 4 per SMSP
#define HB 8           // h-rows owned per scan block (128*8 = 1024)

typedef unsigned long long ull;

// ---------------- device scratch (no allocations allowed) ----------------
__device__ __align__(256) float g_pre0[(size_t)TT * HH * BB]; // [t][h][b], 128 MB
__device__ __align__(256) float g_h1[2][HH * BB];             // ping-pong [h][b]
__device__ __align__(256) float g_h2[2][HH * BB];
__device__ unsigned             g_bar;

// ---------------- packed f32x2 helpers ----------------
#define FFMA2(d, a, b) asm("fma.rn.f32x2 %0, %1, %2, %0;" : "+l"(d) : "l"(a), "l"(b))
#define FADD2(d, a)    asm("add.rn.f32x2 %0, %0, %1;"     : "+l"(d) : "l"(a))

union F4U { float4 f; ull u[2]; };

// Monotone grid barrier (R9-proven): counter zeroed by k_init each launch.
__device__ __forceinline__ void gsync(unsigned n) {
    __threadfence();
    __syncthreads();
    if (threadIdx.x == 0) {
        atomicAdd(&g_bar, 1u);
        const unsigned tgt = n * GRID_SCAN;
        while (*((volatile unsigned*)&g_bar) < tgt) { }
    }
    __syncthreads();
}

// 16 packed FMAs: 8 h-rows (4 float4 of (w,w) pairs) x 4 b (2 packed pairs)
__device__ __forceinline__ void mat16(ull* acc, const float4* W, const ull* su) {
    F4U q0, q1, q2, q3;
    q0.f = W[0]; q1.f = W[1]; q2.f = W[2]; q3.f = W[3];
    FFMA2(acc[ 0], q0.u[0], su[0]); FFMA2(acc[ 1], q0.u[0], su[1]);
    FFMA2(acc[ 2], q0.u[1], su[0]); FFMA2(acc[ 3], q0.u[1], su[1]);
    FFMA2(acc[ 4], q1.u[0], su[0]); FFMA2(acc[ 5], q1.u[0], su[1]);
    FFMA2(acc[ 6], q1.u[1], su[0]); FFMA2(acc[ 7], q1.u[1], su[1]);
    FFMA2(acc[ 8], q2.u[0], su[0]); FFMA2(acc[ 9], q2.u[0], su[1]);
    FFMA2(acc[10], q2.u[1], su[0]); FFMA2(acc[11], q2.u[1], su[1]);
    FFMA2(acc[12], q3.u[0], su[0]); FFMA2(acc[13], q3.u[0], su[1]);
    FFMA2(acc[14], q3.u[1], su[0]); FFMA2(acc[15], q3.u[1], su[1]);
}

// ======================================================================
// Kernel 1: pre0[t][h][b] = sum_e emb[x[b][t]][e]*W_ih0[h][e] + b_ih0[h] + b_hh0[h]
// ======================================================================
__global__ void k_pre0(const int* __restrict__ x, const float* __restrict__ emb,
                       const float* __restrict__ Wih0,
                       const float* __restrict__ bih0, const float* __restrict__ bhh0) {
    extern __shared__ float sm[];
    float*  As  = sm;                       // [300][64]  As[c*64 + b]
    float2* Ws2 = (float2*)(sm + EE * 64);  // [300][64]  (w,w) pairs
    __shared__ int toks[64];

    const int tid   = threadIdx.x;
    const int t     = blockIdx.y;
    const int hbase = blockIdx.x * 64;

    if (tid < 64) toks[tid] = x[tid * TT + t];
    __syncthreads();

    for (int idx = tid; idx < 64 * EE; idx += 256) {
        int r = idx / EE, c = idx - r * EE;
        As[c * 64 + r] = emb[(size_t)toks[r] * EE + c];
        float wv = Wih0[(size_t)(hbase + r) * EE + c];
        Ws2[c * 64 + r] = make_float2(wv, wv);
    }
    __syncthreads();

    const int tx = tid & 15;    // b-quad
    const int ty = tid >> 4;    // h-quad
    ull acc2[4][2];
#pragma unroll
    for (int j = 0; j < 4; j++) { acc2[j][0] = 0ull; acc2[j][1] = 0ull; }

#pragma unroll 4
    for (int c = 0; c < EE; c++) {
        ull a01 = *(const ull*)(As + c * 64 + tx * 4);
        ull a23 = *(const ull*)(As + c * 64 + tx * 4 + 2);
        F4U w01, w23;
        w01.f = *(const float4*)(Ws2 + c * 64 + ty * 4);
        w23.f = *(const float4*)(Ws2 + c * 64 + ty * 4 + 2);
        FFMA2(acc2[0][0], w01.u[0], a01); FFMA2(acc2[0][1], w01.u[0], a23);
        FFMA2(acc2[1][0], w01.u[1], a01); FFMA2(acc2[1][1], w01.u[1], a23);
        FFMA2(acc2[2][0], w23.u[0], a01); FFMA2(acc2[2][1], w23.u[0], a23);
        FFMA2(acc2[3][0], w23.u[1], a01); FFMA2(acc2[3][1], w23.u[1], a23);
    }

#pragma unroll
    for (int j = 0; j < 4; j++) {
        int h = hbase + ty * 4 + j;
        float bs = bih0[h] + bhh0[h];
        F4U o; o.u[0] = acc2[j][0]; o.u[1] = acc2[j][1];
        float4 v = make_float4(o.f.x + bs, o.f.y + bs, o.f.z + bs, o.f.w + bs);
        *(float4*)(&g_pre0[((size_t)t * HH + h) * BB + tx * 4]) = v;
    }
}

// ======================================================================
// Kernel 2: persistent scan, warp-specialized.
//   warps 0..7  (s1): read h1[t-1] over k-range w; acc a1 = Whh0.s1 AND
//                     a2 = Wih1.s1 (both consume the same state data).
//   warps 8..15 (s2): read h2[t-2] over k-range w-8; acc a2 = Whh1.s2.
// State traffic = 512 KB/block/step (each element read once). One grid
// barrier per iter. Two-phase reduction reuses the 32 KB red buffer.
// ======================================================================
__global__ void __launch_bounds__(TPB_SCAN, 1)
k_scan(const float* __restrict__ Whh0, const float* __restrict__ Wih1,
       const float* __restrict__ Whh1,
       const float* __restrict__ bih1, const float* __restrict__ bhh1) {
    extern __shared__ float sm[];
    float2* wp0    = (float2*)sm;            // [1024][8] (w,w) pairs, 64 KB
    float2* wpA    = wp0 + 8192;             // Wih1
    float2* wpB    = wpA + 8192;             // Whh1
    float*  red    = (float*)(wpB + 8192);   // [8 slots][2 mats][8 h][64 b], 32 KB
    float*  bias2s = red + 8192;             // [8]

    const int g    = blockIdx.x;
    const int tid  = threadIdx.x;
    const int w    = tid >> 5;        // 0..15
    const int lane = tid & 31;
    const int bq   = lane >> 1;       // 0..15
    const int kl   = lane & 1;
    const int b4   = bq * 4;

    const bool isS1 = (w < 8);
    const int  kr   = isS1 ? w : (w - 8);   // k-range id 0..7
    const int  k0   = kr * 128 + kl;        // first k; step 2, 64 iters

    // Finale mapping (threads 0..255)
    const int matf = (tid >> 7) & 1;
    const int hlf  = (tid >> 4) & 7;
    const int b0f  = (tid & 15) * 4;

    // Load + transpose + duplicate this block's weight rows (one-time).
    for (int idx = tid; idx < HB * HH; idx += TPB_SCAN) {
        int j = idx >> 10, kk = idx & 1023;
        float v0 = Whh0[(size_t)(g * HB + j) * HH + kk];
        float va = Wih1[(size_t)(g * HB + j) * HH + kk];
        float vb = Whh1[(size_t)(g * HB + j) * HH + kk];
        wp0[kk * 8 + j] = make_float2(v0, v0);
        wpA[kk * 8 + j] = make_float2(va, va);
        wpB[kk * 8 + j] = make_float2(vb, vb);
    }
    if (tid < HB) bias2s[tid] = bih1[g * HB + tid] + bhh1[g * HB + tid];
    __syncthreads();

    unsigned syncno = 0;

    for (int t = 0; t <= TT; t++) {
        const float* s1base = g_h1[(t + 1) & 1];   // h1[t-1]
        const float* s2base = g_h2[t & 1];         // h2[t-2]

        // Early prefetch of this step's pre0 operand for the finale (DRAM).
        float4 pre_pref;
        if (tid < 256 && matf == 0 && t < TT)
            pre_pref = __ldg((const float4*)&g_pre0[((size_t)t * HH + g * HB + hlf) * BB + b0f]);

        ull a1[16], a2[16];
#pragma unroll
        for (int i = 0; i < 16; i++) a2[i] = 0ull;

        if (isS1) {
#pragma unroll
            for (int i = 0; i < 16; i++) a1[i] = 0ull;
            const float*  p1   = s1base + (size_t)k0 * BB + b4;
            const float4* w0f4 = (const float4*)wp0 + (size_t)k0 * 4;
            const float4* wAf4 = (const float4*)wpA + (size_t)k0 * 4;

            F4U buf[2], cur;
            buf[0].f = __ldcg((const float4*)(p1));
            buf[1].f = __ldcg((const float4*)(p1 + 128));
#pragma unroll 4
            for (int i = 0; i < 64; i++) {
                cur = buf[i & 1];
                if (i + 2 < 64) buf[i & 1].f = __ldcg((const float4*)(p1 + (size_t)(i + 2) * 128));
                mat16(a1, w0f4 + (size_t)i * 8, cur.u);
                mat16(a2, wAf4 + (size_t)i * 8, cur.u);
            }
        } else {
            const float*  p2   = s2base + (size_t)k0 * BB + b4;
            const float4* wBf4 = (const float4*)wpB + (size_t)k0 * 4;

            F4U buf[2], cur;
            buf[0].f = __ldcg((const float4*)(p2));
            buf[1].f = __ldcg((const float4*)(p2 + 128));
#pragma unroll 4
            for (int i = 0; i < 64; i++) {
                cur = buf[i & 1];
                if (i + 2 < 64) buf[i & 1].f = __ldcg((const float4*)(p2 + (size_t)(i + 2) * 128));
                mat16(a2, wBf4 + (size_t)i * 8, cur.u);
            }
        }

        // Reduce across klane (adjacent lanes) with 64-bit shfl + packed add.
        if (isS1) {
#pragma unroll
            for (int i = 0; i < 16; i++) {
                ull o1 = __shfl_xor_sync(0xffffffffu, a1[i], 1); FADD2(a1[i], o1);
                ull o2 = __shfl_xor_sync(0xffffffffu, a2[i], 1); FADD2(a2[i], o2);
            }
        } else {
#pragma unroll
            for (int i = 0; i < 16; i++) {
                ull o2 = __shfl_xor_sync(0xffffffffu, a2[i], 1); FADD2(a2[i], o2);
            }
        }

        // ---- Phase 1: s1-warps store a1 (mat0) and a2 part-1 (mat1). ----
        if (isS1 && kl == 0) {
#pragma unroll
            for (int h = 0; h < 8; h++) {
                F4U o;
                o.u[0] = a1[h * 2]; o.u[1] = a1[h * 2 + 1];
                *(float4*)&red[((w * 2 + 0) * 8 + h) * 64 + b4] = o.f;
                o.u[0] = a2[h * 2]; o.u[1] = a2[h * 2 + 1];
                *(float4*)&red[((w * 2 + 1) * 8 + h) * 64 + b4] = o.f;
            }
        }
        __syncthreads();

        // Finale part 1: sum the 8 s1-warp partials into register s.
        float4 s = make_float4(0.f, 0.f, 0.f, 0.f);
        if (tid < 256) {
#pragma unroll
            for (int p = 0; p < 8; p++) {
                float4 v = *(const float4*)&red[((p * 16) + matf * 8 + hlf) * 64 + b0f];
                s.x += v.x; s.y += v.y; s.z += v.z; s.w += v.w;
            }
            if (matf == 0 && t < TT) {
                s.x = tanhf(s.x + pre_pref.x); s.y = tanhf(s.y + pre_pref.y);
                s.z = tanhf(s.z + pre_pref.z); s.w = tanhf(s.w + pre_pref.w);
                __stcg((float4*)&g_h1[t & 1][(g * HB + hlf) * BB + b0f], s);
            }
        }
        __syncthreads();   // part-1 reads complete before mat1 slots overwritten

        // ---- Phase 2: s2-warps store a2 part-2 into the mat1 slots. ----
        if (!isS1 && kl == 0) {
            const int w2 = w - 8;
#pragma unroll
            for (int h = 0; h < 8; h++) {
                F4U o;
                o.u[0] = a2[h * 2]; o.u[1] = a2[h * 2 + 1];
                *(float4*)&red[((w2 * 2 + 1) * 8 + h) * 64 + b4] = o.f;
            }
        }
        __syncthreads();

        // Finale part 2: h2 threads add the 8 s2-warp partials, bias, tanh.
        if (tid < 256 && matf == 1 && t > 0) {
#pragma unroll
            for (int p = 0; p < 8; p++) {
                float4 v = *(const float4*)&red[((p * 16) + 8 + hlf) * 64 + b0f];
                s.x += v.x; s.y += v.y; s.z += v.z; s.w += v.w;
            }
            float bb = bias2s[hlf];
            s.x = tanhf(s.x + bb); s.y = tanhf(s.y + bb);
            s.z = tanhf(s.z + bb); s.w = tanhf(s.w + bb);
            // h2[t-1] -> buffer (t-1)&1 == (t+1)&1
            __stcg((float4*)&g_h2[(t + 1) & 1][(g * HB + hlf) * BB + b0f], s);
        }

        if (t < TT) gsync(++syncno);
    }
}

// ======================================================================
// Kernel 3: out[b] = sigmoid(h2[511][:,b] . W_fc + b_fc).  h2[511] is in buf 1.
// ======================================================================
__global__ void k_fc(const float* __restrict__ Wfc, const float* __restrict__ bfc,
                     float* __restrict__ out) {
    __shared__ float redm[256];
    const int tid = threadIdx.x;
    const int b = tid & 63, part = tid >> 6;
    float s = 0.f;
    for (int hh = part * 256; hh < part * 256 + 256; hh++)
        s += g_h2[1][hh * BB + b] * Wfc[hh];
    redm[tid] = s;
    __syncthreads();
    if (tid < 64) {
        float v = redm[tid] + redm[tid + 64] + redm[tid + 128] + redm[tid + 192] + bfc[0];
        out[b] = 1.f / (1.f + expf(-v));
    }
}

// ======================================================================
// Kernel 0: per-launch reset (determinism across graph replays).
// ======================================================================
__global__ void k_init() {
    int i = blockIdx.x * blockDim.x + threadIdx.x;
    if (i == 0) g_bar = 0u;
    if (i < HH * BB) {
        g_h1[0][i] = 0.f; g_h1[1][i] = 0.f;
        g_h2[0][i] = 0.f; g_h2[1][i] = 0.f;
    }
}

// ======================================================================
extern "C" void kernel_launch(void* const* d_in, const int* in_sizes, int n_in,
                              void* d_out, int out_size) {
    const int*   x    = (const int*)  d_in[0];
    const float* emb  = (const float*)d_in[1];
    const float* Wih0 = (const float*)d_in[2];
    const float* Whh0 = (const float*)d_in[3];
    const float* bih0 = (const float*)d_in[4];
    const float* bhh0 = (const float*)d_in[5];
    const float* Wih1 = (const float*)d_in[6];
    const float* Whh1 = (const float*)d_in[7];
    const float* bih1 = (const float*)d_in[8];
    const float* bhh1 = (const float*)d_in[9];
    const float* Wfc  = (const float*)d_in[10];
    const float* bfc  = (const float*)d_in[11];
    float* out = (float*)d_out;

    const int pre0_smem = (EE * 64) * 4 + (EE * 64) * 8;                 // 230,400 B
    const int scan_smem = (3 * 8192) * 8 + 8192 * 4 + 64;                // 229,504 B
    cudaFuncSetAttribute(k_pre0, cudaFuncAttributeMaxDynamicSharedMemorySize, pre0_smem);
    cudaFuncSetAttribute(k_scan, cudaFuncAttributeMaxDynamicSharedMemorySize, scan_smem);

    k_init<<<(HH * BB + 255) / 256, 256>>>();
    k_pre0<<<dim3(HH / 64, TT), 256, pre0_smem>>>(x, emb, Wih0, bih0, bhh0);
    k_scan<<<GRID_SCAN, TPB_SCAN, scan_smem>>>(Whh0, Wih1, Whh1, bih1, bhh1);
    k_fc<<<1, 256>>>(Wfc, bfc, out);
}